// round 10
// baseline (speedup 1.0000x reference)
#include <cuda_runtime.h>
#include <math.h>

#define BATCH 128
#define SEQ 48
#define FEAT 60
#define NH 5
#define NV 6
#define TWO_PI 6.2831853071795864769f

struct C2 { float re, im; };
struct M2 { C2 m00, m01, m10, m11; };

__device__ __forceinline__ C2 cmul(C2 a, C2 b) {
    C2 r; r.re = a.re*b.re - a.im*b.im; r.im = a.re*b.im + a.im*b.re; return r;
}
__device__ __forceinline__ C2 cadd(C2 a, C2 b) { C2 r{a.re+b.re, a.im+b.im}; return r; }

// U = RZ(t3) * RY(t2) * RX(t1)
__device__ __forceinline__ M2 fuse_zyx(float t1, float t2, float t3) {
    float c1,s1,c2,s2,c3,s3;
    sincosf(0.5f*t1, &s1, &c1);
    sincosf(0.5f*t2, &s2, &c2);
    sincosf(0.5f*t3, &s3, &c3);
    C2 a00{c1,0.f}, a01{0.f,-s1}, a10{0.f,-s1}, a11{c1,0.f};
    C2 m00{c2*a00.re - s2*a10.re, c2*a00.im - s2*a10.im};
    C2 m01{c2*a01.re - s2*a11.re, c2*a01.im - s2*a11.im};
    C2 m10{s2*a00.re + c2*a10.re, s2*a00.im + c2*a10.im};
    C2 m11{s2*a01.re + c2*a11.re, s2*a01.im + c2*a11.im};
    C2 r0{c3,-s3}, r1{c3,s3};
    M2 u;
    u.m00 = cmul(r0,m00); u.m01 = cmul(r0,m01);
    u.m10 = cmul(r1,m10); u.m11 = cmul(r1,m11);
    return u;
}
__device__ __forceinline__ M2 mmul(M2 p, M2 q) {
    M2 r;
    r.m00 = cadd(cmul(p.m00,q.m00), cmul(p.m01,q.m10));
    r.m01 = cadd(cmul(p.m00,q.m01), cmul(p.m01,q.m11));
    r.m10 = cadd(cmul(p.m10,q.m00), cmul(p.m11,q.m10));
    r.m11 = cadd(cmul(p.m10,q.m01), cmul(p.m11,q.m11));
    return r;
}

// ---- cooperative SMEM gate stages: state S[amp][col], stride 33 ----
template<int M>
__device__ __forceinline__ void g1q_s(float* Sre, float* Sim, int col, int w, const M2& g) {
    #pragma unroll
    for (int pp = 0; pp < 4; ++pp) {
        int p = 4*w + pp;
        int i = ((p & ~(M-1)) << 1) | (p & (M-1));
        int j = i | M;
        float ar = Sre[i*33+col], ai = Sim[i*33+col];
        float br = Sre[j*33+col], bi = Sim[j*33+col];
        Sre[i*33+col] = g.m00.re*ar - g.m00.im*ai + g.m01.re*br - g.m01.im*bi;
        Sim[i*33+col] = g.m00.re*ai + g.m00.im*ar + g.m01.re*bi + g.m01.im*br;
        Sre[j*33+col] = g.m10.re*ar - g.m10.im*ai + g.m11.re*br - g.m11.im*bi;
        Sim[j*33+col] = g.m10.re*ai + g.m10.im*ar + g.m11.re*bi + g.m11.im*br;
    }
}
template<int MC, int MT>
__device__ __forceinline__ void gcrx_s(float* Sre, float* Sim, int col, int w, float c, float s) {
    #pragma unroll
    for (int pp = 0; pp < 2; ++pp) {
        int p = 2*w + pp;
        int i = ((p & ~(MT-1)) << 2) | MC | (p & (MT-1));
        int j = i | MT;
        float a0r = Sre[i*33+col], a0i = Sim[i*33+col];
        float a1r = Sre[j*33+col], a1i = Sim[j*33+col];
        Sre[i*33+col] = c*a0r + s*a1i;
        Sim[i*33+col] = c*a0i - s*a1r;
        Sre[j*33+col] = s*a0i + c*a1r;
        Sim[j*33+col] = c*a1i - s*a0r;
    }
}

__device__ __forceinline__ unsigned long long pack2(float lo, float hi) {
    unsigned long long r;
    asm("mov.b64 %0, {%1, %2};" : "=l"(r) : "r"(__float_as_uint(lo)), "r"(__float_as_uint(hi)));
    return r;
}
__device__ __forceinline__ void unpack2(unsigned long long v, float& lo, float& hi) {
    unsigned a, b;
    asm("mov.b64 {%0, %1}, %2;" : "=r"(a), "=r"(b) : "l"(v));
    lo = __uint_as_float(a); hi = __uint_as_float(b);
}
__device__ __forceinline__ void fma2(unsigned long long& acc, unsigned long long a, unsigned long long b) {
    asm("fma.rn.f32x2 %0, %1, %2, %0;" : "+l"(acc) : "l"(a), "l"(b));
}
__device__ __forceinline__ unsigned long long mul2(unsigned long long a, unsigned long long b) {
    unsigned long long r;
    asm("mul.rn.f32x2 %0, %1, %2;" : "=l"(r) : "l"(a), "l"(b));
    return r;
}

__global__ __launch_bounds__(128)
void qrnn_kernel(const float* __restrict__ x,
                 const float* __restrict__ hidden,
                 const float* __restrict__ params,
                 float* __restrict__ out)
{
    const int b   = blockIdx.x;
    const int tid = threadIdx.x;
    const int col = tid & 31;
    const int w   = tid >> 5;

    __shared__ float Sre[32*33];
    __shared__ float Sim[32*33];

    // ======== cooperative precompute of U'' = CRX1*G2*CRX0*G1 (all 128 threads) ========
    {
        M2 h1[5], h2[5];
        #pragma unroll
        for (int q = 0; q < 5; q++) {
            h1[q] = fuse_zyx(params[3*q],    params[3*q+1],    params[3*q+2]);
            h2[q] = fuse_zyx(params[37+3*q], params[37+3*q+1], params[37+3*q+2]);
        }
        float cx[8], sx[8];
        #pragma unroll
        for (int k = 0; k < 8; k++) {
            int l = k >> 2, kk = k & 3;
            sincosf(0.5f*params[l*37 + 15 + kk], &sx[k], &cx[k]);
        }

        #pragma unroll
        for (int r = 0; r < 8; ++r) {
            int i = 8*w + r;
            Sre[i*33 + col] = (i == col) ? 1.f : 0.f;
            Sim[i*33 + col] = 0.f;
        }
        __syncthreads();

        g1q_s<16>(Sre, Sim, col, w, h1[0]); __syncthreads();
        g1q_s< 8>(Sre, Sim, col, w, h1[1]); __syncthreads();
        g1q_s< 4>(Sre, Sim, col, w, h1[2]); __syncthreads();
        g1q_s< 2>(Sre, Sim, col, w, h1[3]); __syncthreads();
        g1q_s< 1>(Sre, Sim, col, w, h1[4]); __syncthreads();
        gcrx_s<16,8>(Sre, Sim, col, w, cx[0], sx[0]); __syncthreads();
        gcrx_s< 8,4>(Sre, Sim, col, w, cx[1], sx[1]); __syncthreads();
        gcrx_s< 4,2>(Sre, Sim, col, w, cx[2], sx[2]); __syncthreads();
        gcrx_s< 2,1>(Sre, Sim, col, w, cx[3], sx[3]); __syncthreads();
        g1q_s<16>(Sre, Sim, col, w, h2[0]); __syncthreads();
        g1q_s< 8>(Sre, Sim, col, w, h2[1]); __syncthreads();
        g1q_s< 4>(Sre, Sim, col, w, h2[2]); __syncthreads();
        g1q_s< 2>(Sre, Sim, col, w, h2[3]); __syncthreads();
        g1q_s< 1>(Sre, Sim, col, w, h2[4]); __syncthreads();
        gcrx_s<16,8>(Sre, Sim, col, w, cx[4], sx[4]); __syncthreads();
        gcrx_s< 8,4>(Sre, Sim, col, w, cx[5], sx[5]); __syncthreads();
        gcrx_s< 4,2>(Sre, Sim, col, w, cx[6], sx[6]); __syncthreads();
        gcrx_s< 2,1>(Sre, Sim, col, w, cx[7], sx[7]); __syncthreads();
    }

    if (tid < 32) {
        // ================= warp 0: hidden recurrence loop =================
        const int lane = tid;
        const bool special = (__popc(lane) == 1) && (lane <= 16);
        const int q_of_lane = special ? (__clz(lane) - 27) : 0;   // lane16->q0 ... lane1->q4

        // read ROW lane of U'', fold embed phase (-i)^popc(col), pack column pairs
        unsigned long long PRr[16], PRi[16];
        #pragma unroll
        for (int j2 = 0; j2 < 16; ++j2) {
            float re0 = Sre[lane*33 + 2*j2],   im0 = Sim[lane*33 + 2*j2];
            float re1 = Sre[lane*33 + 2*j2+1], im1 = Sim[lane*33 + 2*j2+1];
            int k0 = __popc(2*j2) & 3, k1 = __popc(2*j2+1) & 3;
            float a0, b0, a1, b1;
            if (k0 == 0)      { a0 =  re0; b0 =  im0; }
            else if (k0 == 1) { a0 =  im0; b0 = -re0; }
            else if (k0 == 2) { a0 = -re0; b0 = -im0; }
            else              { a0 = -im0; b0 =  re0; }
            if (k1 == 0)      { a1 =  re1; b1 =  im1; }
            else if (k1 == 1) { a1 =  im1; b1 = -re1; }
            else if (k1 == 2) { a1 = -re1; b1 = -im1; }
            else              { a1 = -im1; b1 =  re1; }
            PRr[j2] = pack2(a0, a1);
            PRi[j2] = pack2(b0, b1);
        }

        float z = special ? hidden[b*NH + q_of_lane] : 0.f;
        const float SCALE   = 1073741824.0f;        // 2^30
        const float INVSCALE = 9.313225746154785e-10f; // 2^-30

        #pragma unroll 1
        for (int t = 0; t < SEQ; ++t) {
            // ---- sincos on special lanes; broadcast 5 (c,s) pairs ----
            float cc, ss;
            __sincosf(0.5f*z, &ss, &cc);
            float c0 = __shfl_sync(0xffffffffu, cc, 16), s0 = __shfl_sync(0xffffffffu, ss, 16);
            float c1 = __shfl_sync(0xffffffffu, cc,  8), s1 = __shfl_sync(0xffffffffu, ss,  8);
            float c2 = __shfl_sync(0xffffffffu, cc,  4), s2 = __shfl_sync(0xffffffffu, ss,  4);
            float c3 = __shfl_sync(0xffffffffu, cc,  2), s3 = __shfl_sync(0xffffffffu, ss,  2);
            float c4 = __shfl_sync(0xffffffffu, cc,  1), s4 = __shfl_sync(0xffffffffu, ss,  1);

            // ---- group products over qubits 0..2 (8 groups), pair consts over q3,q4 ----
            float g01_0 = c0*c1, g01_1 = c0*s1, g01_2 = s0*c1, g01_3 = s0*s1;
            float g0 = g01_0*c2, g1 = g01_0*s2, g2 = g01_1*c2, g3 = g01_1*s2;
            float g4 = g01_2*c2, g5 = g01_2*s2, g6 = g01_3*c2, g7 = g01_3*s2;
            const unsigned long long pa = pack2(c3*c4, c3*s4);
            const unsigned long long pb = pack2(s3*c4, s3*s4);

            // ---- matvec amp' = U'' * m, 8 accumulators (dep chains of 4) ----
            unsigned long long aR0=0ull, aR1=0ull, aI0=0ull, aI1=0ull;
            unsigned long long bR0=0ull, bR1=0ull, bI0=0ull, bI1=0ull;
            #define STEPA(k, g)                                            \
            {                                                              \
                unsigned long long gg = pack2(g, g);                       \
                unsigned long long m0 = mul2(gg, pa);                      \
                unsigned long long m1 = mul2(gg, pb);                      \
                fma2(aR0, PRr[2*(k)],   m0);                               \
                fma2(aI0, PRi[2*(k)],   m0);                               \
                fma2(aR1, PRr[2*(k)+1], m1);                               \
                fma2(aI1, PRi[2*(k)+1], m1);                               \
            }
            #define STEPB(k, g)                                            \
            {                                                              \
                unsigned long long gg = pack2(g, g);                       \
                unsigned long long m0 = mul2(gg, pa);                      \
                unsigned long long m1 = mul2(gg, pb);                      \
                fma2(bR0, PRr[2*(k)],   m0);                               \
                fma2(bI0, PRi[2*(k)],   m0);                               \
                fma2(bR1, PRr[2*(k)+1], m1);                               \
                fma2(bI1, PRi[2*(k)+1], m1);                               \
            }
            STEPA(0, g0) STEPB(1, g1) STEPA(2, g2) STEPB(3, g3)
            STEPA(4, g4) STEPB(5, g5) STEPA(6, g6) STEPB(7, g7)
            #undef STEPA
            #undef STEPB

            float x0,x1,y0,y1,u0,u1,v0,v1;
            float p0,p1,q0,q1,r0f,r1f,s0f,s1f;
            unpack2(aR0,x0,x1); unpack2(aR1,y0,y1);
            unpack2(bR0,p0,p1); unpack2(bR1,q0,q1);
            unpack2(aI0,u0,u1); unpack2(aI1,v0,v1);
            unpack2(bI0,r0f,r1f); unpack2(bI1,s0f,s1f);
            float nar = ((x0+x1)+(y0+y1)) + ((p0+p1)+(q0+q1));
            float nai = ((u0+u1)+(v0+v1)) + ((r0f+r1f)+(s0f+s1f));

            // ---- measure: fixed-point + 5 independent REDUX.SYNC.ADD.S32 ----
            float p = fmaf(nar, nar, nai*nai);
            int ip = __float2int_rn(p * SCALE);
            int t0 = __reduce_add_sync(0xffffffffu, (lane & 16) ? -ip : ip);
            int t1 = __reduce_add_sync(0xffffffffu, (lane &  8) ? -ip : ip);
            int t2 = __reduce_add_sync(0xffffffffu, (lane &  4) ? -ip : ip);
            int t3 = __reduce_add_sync(0xffffffffu, (lane &  2) ? -ip : ip);
            int t4 = __reduce_add_sync(0xffffffffu, (lane &  1) ? -ip : ip);

            int rq = t0;
            rq = (q_of_lane == 1) ? t1 : rq;
            rq = (q_of_lane == 2) ? t2 : rq;
            rq = (q_of_lane == 3) ? t3 : rq;
            rq = (q_of_lane == 4) ? t4 : rq;
            z = special ? ((float)rq * INVSCALE) : 0.f;
        }
        if (special) out[BATCH*SEQ*NV + b*NH + q_of_lane] = z;

    } else {
        // ============ warps 1-3: closed-form outputs for this batch ============
        const int t = tid - 32;
        if (t >= SEQ) return;

        float Cc[6], Dd[6], Ee[6];
        #pragma unroll
        for (int q = 0; q < 6; q++) {
            M2 u0 = fuse_zyx(params[19+3*q],    params[20+3*q],    params[21+3*q]);
            M2 u1 = fuse_zyx(params[37+19+3*q], params[37+20+3*q], params[37+21+3*q]);
            M2 M = mmul(u1, u0);
            float h00 = (M.m00.re*M.m00.re + M.m00.im*M.m00.im)
                      - (M.m10.re*M.m10.re + M.m10.im*M.m10.im);
            float h11 = (M.m01.re*M.m01.re + M.m01.im*M.m01.im)
                      - (M.m11.re*M.m11.re + M.m11.im*M.m11.im);
            float imh01 = (M.m00.re*M.m01.im - M.m00.im*M.m01.re)
                        - (M.m10.re*M.m11.im - M.m10.im*M.m11.re);
            Cc[q] = 0.5f*(h00 + h11);
            Dd[q] = 0.5f*(h00 - h11);
            Ee[q] = imh01;
        }

        const int P = b * SEQ + t;
        const float4* x4 = (const float4*)(x + (size_t)P * FEAT);
        float vals[60];
        #pragma unroll
        for (int k = 0; k < 15; k++) {
            float4 v4 = x4[k];
            vals[4*k+0] = v4.x; vals[4*k+1] = v4.y;
            vals[4*k+2] = v4.z; vals[4*k+3] = v4.w;
        }
        float pooled[6];
        #pragma unroll
        for (int v = 0; v < 6; v++) {
            float s = 0.f;
            #pragma unroll
            for (int j = 0; j < 10; j++) s += vals[v*10 + j];
            pooled[v] = 0.1f * s;
        }
        float mn = pooled[0], mx = pooled[0];
        #pragma unroll
        for (int v = 1; v < 6; v++) {
            mn = fminf(mn, pooled[v]);
            mx = fmaxf(mx, pooled[v]);
        }
        float scale = TWO_PI / (mx - mn + 1e-8f);
        #pragma unroll
        for (int v = 0; v < 6; v++) {
            float a = scale * (pooled[v] - mn);
            float sa, ca;
            sincosf(a, &sa, &ca);
            out[(size_t)P*6 + v] = Cc[v] + Dd[v]*ca + Ee[v]*sa;
        }
    }
}

extern "C" void kernel_launch(void* const* d_in, const int* in_sizes, int n_in,
                              void* d_out, int out_size) {
    const float* x      = (const float*)d_in[0];
    const float* hidden = (const float*)d_in[1];
    const float* params = (const float*)d_in[2];
    float* out = (float*)d_out;
    qrnn_kernel<<<BATCH, 128>>>(x, hidden, params, out);
}